// round 6
// baseline (speedup 1.0000x reference)
#include <cuda_runtime.h>
#include <stdint.h>

#define N_WORDS     8
#define HASH_BITS   11
#define HASH_SIZE   (1 << HASH_BITS)      // 2048 slots, 8 KB
#define HASH_MASK   (HASH_SIZE - 1)
#define MAX_CLASSES 1024                  // shared copy: 32 KB
#define THREADS     256

__device__ __forceinline__ uint32_t hash8(const uint32_t k[N_WORDS]) {
    uint32_t h = 2166136261u;
    #pragma unroll
    for (int j = 0; j < N_WORDS; ++j) h = (h ^ k[j]) * 16777619u;
    h ^= h >> 15; h *= 0x2c1b3c6du;
    h ^= h >> 12; h *= 0x297a2d39u;
    h ^= h >> 15;
    return h;
}

__global__ __launch_bounds__(THREADS)
void encode_kernel(const int* __restrict__ x,
                   const int* __restrict__ classes,
                   float* __restrict__ out,          // output dtype is FLOAT32
                   int n_rows, int n_classes) {
    __shared__ int s_tab[HASH_SIZE];              // slot -> class idx, or -1
    __shared__ int s_cls[MAX_CLASSES * N_WORDS];  // class table copy

    const int tid = threadIdx.x;
    const bool use_smem = (n_classes <= MAX_CLASSES);

    for (int i = tid; i < HASH_SIZE; i += THREADS) s_tab[i] = -1;
    if (use_smem) {
        const int total = n_classes * N_WORDS;
        for (int i = tid; i < total; i += THREADS) s_cls[i] = classes[i];
    }
    __syncthreads();

    const int* cls = use_smem ? s_cls : classes;

    // Insert every class (bounded linear probing; keys unique).
    for (int c = tid; c < n_classes; c += THREADS) {
        uint32_t k[N_WORDS];
        #pragma unroll
        for (int j = 0; j < N_WORDS; ++j) k[j] = (uint32_t)cls[c * N_WORDS + j];
        uint32_t h = hash8(k) & HASH_MASK;
        for (int p = 0; p < HASH_SIZE; ++p) {
            if (atomicCAS(&s_tab[h], -1, c) == -1) break;
            h = (h + 1) & HASH_MASK;
        }
    }
    __syncthreads();

    const int r = blockIdx.x * THREADS + tid;
    if (r >= n_rows) return;

    // Scalar 32-bit loads (no alignment assumptions).
    uint32_t k[N_WORDS];
    #pragma unroll
    for (int j = 0; j < N_WORDS; ++j) k[j] = (uint32_t)x[(size_t)r * N_WORDS + j];

    // Hash probe with full-key verification.
    int result = -1;
    uint32_t h = hash8(k) & HASH_MASK;
    for (int p = 0; p < HASH_SIZE; ++p) {
        int c = s_tab[h];
        if (c < 0) break;
        bool match = true;
        #pragma unroll
        for (int j = 0; j < N_WORDS; ++j)
            match &= ((uint32_t)cls[c * N_WORDS + j] == k[j]);
        if (match) { result = c; break; }
        h = (h + 1) & HASH_MASK;
    }

    // Guaranteed fallback: first ascending match == argmax semantics; 0 if none.
    if (result < 0) {
        for (int c = 0; c < n_classes; ++c) {
            bool match = true;
            #pragma unroll
            for (int j = 0; j < N_WORDS; ++j)
                match &= ((uint32_t)cls[c * N_WORDS + j] == k[j]);
            if (match) { result = c; break; }
        }
        if (result < 0) result = 0;
    }

    out[r] = (float)result;   // labels 0..C-1 are exactly representable in fp32
}

extern "C" void kernel_launch(void* const* d_in, const int* in_sizes, int n_in,
                              void* d_out, int out_size) {
    // x is the large input (one output per row); classes_table is the small one.
    int xi = 0, ci = 1;
    if (n_in >= 2 && in_sizes[1] > in_sizes[0]) { xi = 1; ci = 0; }

    const int* x       = (const int*)d_in[xi];
    const int* classes = (const int*)d_in[ci];
    float* out         = (float*)d_out;

    int rows_from_x = in_sizes[xi] / N_WORDS;
    int n_rows = (out_size < rows_from_x) ? out_size : rows_from_x;
    int n_classes = in_sizes[ci] / N_WORDS;

    int blocks = (n_rows + THREADS - 1) / THREADS;
    if (blocks < 1) blocks = 1;
    encode_kernel<<<blocks, THREADS>>>(x, classes, out, n_rows, n_classes);
}